// round 16
// baseline (speedup 1.0000x reference)
#include <cuda_runtime.h>
#include <cuda_fp16.h>

#define EMBED 128
#define ATTR 25
#define REM 28
#define PAIR_PAD 29                  // coprime with 32 -> conflict-free LDS
#define NLEVEL 50
#define NCOMB 240                    // 2*2*3*20

// fp16 projected tables (b folded into combined rows); 74.2 KB total -> L2 hot
__device__ __half g_Lh[NLEVEL * EMBED];
__device__ __half g_Ch[NCOMB * EMBED];

// Grid-barrier state. Two barriers per launch -> g_sense returns to 0 each
// replay: deterministic under graph capture.
__device__ unsigned g_count = 0;
__device__ volatile unsigned g_sense = 0;

// smem float offsets for staged raw tables (phase A blocks only)
#define S_LVL  0                               // level blocks: 1250 floats
#define S_TYP  0                               // combined blocks reuse same smem
#define S_FEA  (S_TYP + 2 * ATTR)
#define S_EXC  (S_FEA + 2 * ATTR)
#define S_PAI  (S_EXC + 3 * ATTR)
#define S_TOTAL 1280                           // max(1250, 755) rounded up

__device__ __forceinline__ void grid_barrier(unsigned nblocks, unsigned* sense_sm) {
    __syncthreads();
    if (threadIdx.x == 0) {
        unsigned want = (*sense_sm ^= 1u);
        __threadfence();                       // publish prior writes
        unsigned arrived = atomicAdd(&g_count, 1u);
        if (arrived == nblocks - 1u) {
            g_count = 0u;
            __threadfence();
            g_sense = want;                    // release
        } else {
            while (g_sense != want) __nanosleep(40);
        }
    }
    __syncthreads();
    __threadfence();                           // acquire
}

__global__ void __launch_bounds__(256, 6)
fused_all_kernel(const float* __restrict__ level_tab,
                 const float* __restrict__ type_tab,
                 const float* __restrict__ feature_tab,
                 const float* __restrict__ exchange_tab,
                 const float* __restrict__ pair_tab,
                 const float* __restrict__ W,
                 const float* __restrict__ b,
                 const int* __restrict__ level_idx,
                 const int* __restrict__ type_idx,
                 const int* __restrict__ feature_idx,
                 const int* __restrict__ exchange_idx,
                 const int* __restrict__ pair_idx,
                 float4* __restrict__ out, int n)
{
    __shared__ float sm[S_TOTAL];
    __shared__ unsigned sense_sm_arr[1];
    if (threadIdx.x == 0) sense_sm_arr[0] = 0u;

    const int tid  = threadIdx.x;
    const int lane = tid & 31;
    const unsigned nblocks = gridDim.x;

    // ====== Phase A: project base tables to fp16 (blocks 0..159; 1 task/warp) ======
    if (blockIdx.x < 160) {
        const int task = ((int)blockIdx.x << 3) + (tid >> 5);   // 0..1279
        if (blockIdx.x < 32) {
            // level blocks: stage only level_tab (1250 floats)
            for (int i = tid; i < NLEVEL * ATTR; i += 256) sm[S_LVL + i] = level_tab[i];
            __syncthreads();
            int e = task >> 1;
            int r = ((task & 1) << 5) + lane;
            if (r < NLEVEL) {
                const float* wrow = W + e * EMBED;        // broadcast
                const float* lt = sm + S_LVL + r * ATTR;  // stride-25 LDS, conflict-free
                float s0 = 0.f, s1 = 0.f, s2 = 0.f, s3 = 0.f;
                #pragma unroll
                for (int k = 0; k < 24; k += 4) {
                    s0 += lt[k]     * wrow[k];
                    s1 += lt[k + 1] * wrow[k + 1];
                    s2 += lt[k + 2] * wrow[k + 2];
                    s3 += lt[k + 3] * wrow[k + 3];
                }
                s0 += lt[24] * wrow[24];
                g_Lh[r * EMBED + e] = __float2half_rn((s0 + s1) + (s2 + s3));
            }
        } else {
            // combined blocks: stage only the small tables (755 floats)
            for (int i = tid; i < 2 * ATTR; i += 256) sm[S_TYP + i] = type_tab[i];
            for (int i = tid; i < 2 * ATTR; i += 256) sm[S_FEA + i] = feature_tab[i];
            for (int i = tid; i < 3 * ATTR; i += 256) sm[S_EXC + i] = exchange_tab[i];
            for (int i = tid; i < 20 * REM; i += 256) {
                int p = i / REM, k = i - p * REM;
                sm[S_PAI + p * PAIR_PAD + k] = pair_tab[i];
            }
            __syncthreads();
            int tt = task - 256;
            int e  = tt >> 3;
            int c  = ((tt & 7) << 5) + lane;
            if (c < NCOMB) {
                int p = c % 20, x = (c / 20) % 3, f = (c / 60) % 2, t = c / 120;
                const float* wrow = W + e * EMBED;
                const float* ta = sm + S_TYP + t * ATTR;
                const float* fa = sm + S_FEA + f * ATTR;
                const float* xa = sm + S_EXC + x * ATTR;
                const float* pa = sm + S_PAI + p * PAIR_PAD;
                float s0 = b[e], s1 = 0.f, s2 = 0.f, s3 = 0.f;
                #pragma unroll
                for (int k = 0; k < ATTR; k++) {
                    s0 += ta[k] * wrow[25 + k];
                    s1 += fa[k] * wrow[50 + k];
                    s2 += xa[k] * wrow[75 + k];
                }
                #pragma unroll
                for (int k = 0; k < REM; k++)
                    s3 += pa[k] * wrow[100 + k];
                g_Ch[c * EMBED + e] = __float2half_rn((s0 + s1) + (s2 + s3));
            }
        }
    }

    // ====== Pre-barrier prefetch: iteration-0 indices (table-independent) ======
    const int warp   = (blockIdx.x * 256 + tid) >> 5;
    const int nwarps = (nblocks * 256) >> 5;
    const int stride = nwarps * 4;
    int r = warp * 4;

    int4 L, T, F, X, P;
    bool have = (r + 3 < n);
    if (have) {
        L = *reinterpret_cast<const int4*>(level_idx + r);
        T = *reinterpret_cast<const int4*>(type_idx + r);
        F = *reinterpret_cast<const int4*>(feature_idx + r);
        X = *reinterpret_cast<const int4*>(exchange_idx + r);
        P = *reinterpret_cast<const int4*>(pair_idx + r);
    }

    grid_barrier(nblocks, sense_sm_arr);    // sense -> 1; idx loads land during wait

    // ====== Phase C: streaming gather, 2 fp16 row-loads per output row ======
    {
        const uint2* L2h = reinterpret_cast<const uint2*>(g_Lh);   // 32 uint2 per row
        const uint2* C2h = reinterpret_cast<const uint2*>(g_Ch);

        while (have) {
            int l[4] = {L.x, L.y, L.z, L.w};
            int t[4] = {T.x, T.y, T.z, T.w};
            int f[4] = {F.x, F.y, F.z, F.w};
            int x[4] = {X.x, X.y, X.z, X.w};
            int p[4] = {P.x, P.y, P.z, P.w};

            uint2 hvA[4], hvQ[4];
            #pragma unroll
            for (int k = 0; k < 4; k++) {
                int c = ((t[k] * 2 + f[k]) * 3 + x[k]) * 20 + p[k];
                hvA[k] = __ldg(&L2h[l[k] * 32 + lane]);
                hvQ[k] = __ldg(&C2h[c * 32 + lane]);
            }

            const int rcur = r;
            r += stride;
            have = (r + 3 < n);
            if (have) {                          // load next batch before stores
                L = *reinterpret_cast<const int4*>(level_idx + r);
                T = *reinterpret_cast<const int4*>(type_idx + r);
                F = *reinterpret_cast<const int4*>(feature_idx + r);
                X = *reinterpret_cast<const int4*>(exchange_idx + r);
                P = *reinterpret_cast<const int4*>(pair_idx + r);
            }

            #pragma unroll
            for (int k = 0; k < 4; k++) {
                const __half2* ah = reinterpret_cast<const __half2*>(&hvA[k]);
                const __half2* qh = reinterpret_cast<const __half2*>(&hvQ[k]);
                float2 a0 = __half22float2(ah[0]);
                float2 a1 = __half22float2(ah[1]);
                float2 q0 = __half22float2(qh[0]);
                float2 q1 = __half22float2(qh[1]);
                float4 s;
                s.x = a0.x + q0.x;
                s.y = a0.y + q0.y;
                s.z = a1.x + q1.x;
                s.w = a1.y + q1.y;
                __stcs(out + (size_t)(rcur + k) * 32 + lane, s);
            }
        }
        for (; r < n; r++) {   // tail
            int c = ((type_idx[r] * 2 + feature_idx[r]) * 3 + exchange_idx[r]) * 20
                  + pair_idx[r];
            uint2 A = __ldg(&L2h[level_idx[r] * 32 + lane]);
            uint2 Q = __ldg(&C2h[c * 32 + lane]);
            const __half2* ah = reinterpret_cast<const __half2*>(&A);
            const __half2* qh = reinterpret_cast<const __half2*>(&Q);
            float2 a0 = __half22float2(ah[0]);
            float2 a1 = __half22float2(ah[1]);
            float2 q0 = __half22float2(qh[0]);
            float2 q1 = __half22float2(qh[1]);
            float4 s;
            s.x = a0.x + q0.x;
            s.y = a0.y + q0.y;
            s.z = a1.x + q1.x;
            s.w = a1.y + q1.y;
            out[(size_t)r * 32 + lane] = s;
        }
    }

    // Trailing barrier: restores g_sense to 0 for the next graph replay.
    grid_barrier(nblocks, sense_sm_arr);    // sense -> 0
}

extern "C" void kernel_launch(void* const* d_in, const int* in_sizes, int n_in,
                              void* d_out, int out_size) {
    const float* level_tab    = (const float*)d_in[0];
    const float* type_tab     = (const float*)d_in[1];
    const float* feature_tab  = (const float*)d_in[2];
    const float* exchange_tab = (const float*)d_in[3];
    const float* pair_tab     = (const float*)d_in[4];
    const float* W            = (const float*)d_in[5];
    const float* b            = (const float*)d_in[6];
    const int* level_idx      = (const int*)d_in[7];
    const int* type_idx       = (const int*)d_in[8];
    const int* feature_idx    = (const int*)d_in[9];
    const int* exchange_idx   = (const int*)d_in[10];
    const int* pair_idx       = (const int*)d_in[11];

    int n = in_sizes[7];   // N rows

    int sm_count = 148;
    cudaDeviceGetAttribute(&sm_count, cudaDevAttrMultiProcessorCount, 0);

    // 6 blocks/SM x 256 threads: ALL blocks resident -> grid barrier is safe.
    fused_all_kernel<<<6 * sm_count, 256>>>(
        level_tab, type_tab, feature_tab, exchange_tab, pair_tab, W, b,
        level_idx, type_idx, feature_idx, exchange_idx, pair_idx,
        (float4*)d_out, n);
}

// round 17
// speedup vs baseline: 1.4756x; 1.4756x over previous
#include <cuda_runtime.h>
#include <cuda_fp16.h>

#define EMBED 128
#define ATTR 25
#define REM 28
#define PAIR_PAD 29                  // coprime with 32 -> conflict-free LDS
#define NLEVEL 50
#define NCOMB 240                    // 2*2*3*20

// fp16 projected tables (b folded into combined rows); 74.2 KB total -> L2 hot
__device__ __half g_Lh[NLEVEL * EMBED];
__device__ __half g_Ch[NCOMB * EMBED];

// Grid-barrier state. Two barriers per launch -> g_sense returns to 0 each
// replay: deterministic under graph capture.
__device__ unsigned g_count = 0;
__device__ volatile unsigned g_sense = 0;

// smem float offsets (phase A blocks only; level/combined blocks reuse region)
#define S_LVL  0                               // level blocks: 1250 floats
#define S_TYP  0
#define S_FEA  (S_TYP + 2 * ATTR)
#define S_EXC  (S_FEA + 2 * ATTR)
#define S_PAI  (S_EXC + 3 * ATTR)
#define S_TOTAL 1280                           // max(1250, 755)

__device__ __forceinline__ void grid_barrier(unsigned nblocks, unsigned* sense_sm) {
    __syncthreads();
    if (threadIdx.x == 0) {
        unsigned want = (*sense_sm ^= 1u);
        __threadfence();                       // publish prior writes
        unsigned arrived = atomicAdd(&g_count, 1u);
        if (arrived == nblocks - 1u) {
            g_count = 0u;
            __threadfence();
            g_sense = want;                    // release
        } else {
            while (g_sense != want) __nanosleep(40);
        }
    }
    __syncthreads();
    __threadfence();                           // acquire
}

__global__ void __launch_bounds__(256, 6)
fused_all_kernel(const float* __restrict__ level_tab,
                 const float* __restrict__ type_tab,
                 const float* __restrict__ feature_tab,
                 const float* __restrict__ exchange_tab,
                 const float* __restrict__ pair_tab,
                 const float* __restrict__ W,
                 const float* __restrict__ b,
                 const int* __restrict__ level_idx,
                 const int* __restrict__ type_idx,
                 const int* __restrict__ feature_idx,
                 const int* __restrict__ exchange_idx,
                 const int* __restrict__ pair_idx,
                 float4* __restrict__ out, int n)
{
    __shared__ float sm[S_TOTAL];
    __shared__ unsigned sense_sm_arr[1];
    if (threadIdx.x == 0) sense_sm_arr[0] = 0u;

    const int tid  = threadIdx.x;
    const int lane = tid & 31;
    const unsigned nblocks = gridDim.x;

    // ====== Phase A: project base tables to fp16 (blocks 0..159; 1 task/warp) ======
    if (blockIdx.x < 160) {
        const int task = ((int)blockIdx.x << 3) + (tid >> 5);   // 0..1279
        if (blockIdx.x < 32) {
            // level blocks: stage only level_tab (1250 floats)
            for (int i = tid; i < NLEVEL * ATTR; i += 256) sm[S_LVL + i] = level_tab[i];
            __syncthreads();
            int e = task >> 1;
            int r = ((task & 1) << 5) + lane;
            if (r < NLEVEL) {
                const float* wrow = W + e * EMBED;        // broadcast
                const float* lt = sm + S_LVL + r * ATTR;  // stride-25 LDS, conflict-free
                float s0 = 0.f, s1 = 0.f, s2 = 0.f, s3 = 0.f;
                #pragma unroll
                for (int k = 0; k < 24; k += 4) {
                    s0 += lt[k]     * wrow[k];
                    s1 += lt[k + 1] * wrow[k + 1];
                    s2 += lt[k + 2] * wrow[k + 2];
                    s3 += lt[k + 3] * wrow[k + 3];
                }
                s0 += lt[24] * wrow[24];
                g_Lh[r * EMBED + e] = __float2half_rn((s0 + s1) + (s2 + s3));
            }
        } else {
            // combined blocks: stage only the small tables (755 floats)
            for (int i = tid; i < 2 * ATTR; i += 256) sm[S_TYP + i] = type_tab[i];
            for (int i = tid; i < 2 * ATTR; i += 256) sm[S_FEA + i] = feature_tab[i];
            for (int i = tid; i < 3 * ATTR; i += 256) sm[S_EXC + i] = exchange_tab[i];
            for (int i = tid; i < 20 * REM; i += 256) {
                int p = i / REM, k = i - p * REM;
                sm[S_PAI + p * PAIR_PAD + k] = pair_tab[i];
            }
            __syncthreads();
            int tt = task - 256;
            int e  = tt >> 3;
            int c  = ((tt & 7) << 5) + lane;
            if (c < NCOMB) {
                int p = c % 20, x = (c / 20) % 3, f = (c / 60) % 2, t = c / 120;
                const float* wrow = W + e * EMBED;
                const float* ta = sm + S_TYP + t * ATTR;
                const float* fa = sm + S_FEA + f * ATTR;
                const float* xa = sm + S_EXC + x * ATTR;
                const float* pa = sm + S_PAI + p * PAIR_PAD;
                float s0 = b[e], s1 = 0.f, s2 = 0.f, s3 = 0.f;
                #pragma unroll
                for (int k = 0; k < ATTR; k++) {
                    s0 += ta[k] * wrow[25 + k];
                    s1 += fa[k] * wrow[50 + k];
                    s2 += xa[k] * wrow[75 + k];
                }
                #pragma unroll
                for (int k = 0; k < REM; k++)
                    s3 += pa[k] * wrow[100 + k];
                g_Ch[c * EMBED + e] = __float2half_rn((s0 + s1) + (s2 + s3));
            }
        }
    }

    grid_barrier(nblocks, sense_sm_arr);    // sense -> 1

    // ====== Phase C: streaming gather — EXACT R15 loop body (proven 92.9us) ======
    {
        const uint2* L2h = reinterpret_cast<const uint2*>(g_Lh);   // 32 uint2 per row
        const uint2* C2h = reinterpret_cast<const uint2*>(g_Ch);
        const int warp   = (blockIdx.x * 256 + tid) >> 5;
        const int nwarps = (nblocks * 256) >> 5;

        int r = warp * 4;
        const int stride = nwarps * 4;

        for (; r + 3 < n; r += stride) {
            int4 L = *reinterpret_cast<const int4*>(level_idx + r);
            int4 T = *reinterpret_cast<const int4*>(type_idx + r);
            int4 F = *reinterpret_cast<const int4*>(feature_idx + r);
            int4 X = *reinterpret_cast<const int4*>(exchange_idx + r);
            int4 P = *reinterpret_cast<const int4*>(pair_idx + r);

            int l[4] = {L.x, L.y, L.z, L.w};
            int t[4] = {T.x, T.y, T.z, T.w};
            int f[4] = {F.x, F.y, F.z, F.w};
            int x[4] = {X.x, X.y, X.z, X.w};
            int p[4] = {P.x, P.y, P.z, P.w};

            uint2 hvA[4], hvQ[4];
            #pragma unroll
            for (int k = 0; k < 4; k++) {
                int c = ((t[k] * 2 + f[k]) * 3 + x[k]) * 20 + p[k];
                hvA[k] = __ldg(&L2h[l[k] * 32 + lane]);
                hvQ[k] = __ldg(&C2h[c * 32 + lane]);
            }
            #pragma unroll
            for (int k = 0; k < 4; k++) {
                const __half2* ah = reinterpret_cast<const __half2*>(&hvA[k]);
                const __half2* qh = reinterpret_cast<const __half2*>(&hvQ[k]);
                float2 a0 = __half22float2(ah[0]);
                float2 a1 = __half22float2(ah[1]);
                float2 q0 = __half22float2(qh[0]);
                float2 q1 = __half22float2(qh[1]);
                float4 s;
                s.x = a0.x + q0.x;
                s.y = a0.y + q0.y;
                s.z = a1.x + q1.x;
                s.w = a1.y + q1.y;
                __stcs(out + (size_t)(r + k) * 32 + lane, s);
            }
        }
        for (; r < n; r++) {   // tail
            int c = ((type_idx[r] * 2 + feature_idx[r]) * 3 + exchange_idx[r]) * 20
                  + pair_idx[r];
            uint2 A = __ldg(&L2h[level_idx[r] * 32 + lane]);
            uint2 Q = __ldg(&C2h[c * 32 + lane]);
            const __half2* ah = reinterpret_cast<const __half2*>(&A);
            const __half2* qh = reinterpret_cast<const __half2*>(&Q);
            float2 a0 = __half22float2(ah[0]);
            float2 a1 = __half22float2(ah[1]);
            float2 q0 = __half22float2(qh[0]);
            float2 q1 = __half22float2(qh[1]);
            float4 s;
            s.x = a0.x + q0.x;
            s.y = a0.y + q0.y;
            s.z = a1.x + q1.x;
            s.w = a1.y + q1.y;
            out[(size_t)r * 32 + lane] = s;
        }
    }

    // Trailing barrier: restores g_sense to 0 for the next graph replay.
    grid_barrier(nblocks, sense_sm_arr);    // sense -> 0
}

extern "C" void kernel_launch(void* const* d_in, const int* in_sizes, int n_in,
                              void* d_out, int out_size) {
    const float* level_tab    = (const float*)d_in[0];
    const float* type_tab     = (const float*)d_in[1];
    const float* feature_tab  = (const float*)d_in[2];
    const float* exchange_tab = (const float*)d_in[3];
    const float* pair_tab     = (const float*)d_in[4];
    const float* W            = (const float*)d_in[5];
    const float* b            = (const float*)d_in[6];
    const int* level_idx      = (const int*)d_in[7];
    const int* type_idx       = (const int*)d_in[8];
    const int* feature_idx    = (const int*)d_in[9];
    const int* exchange_idx   = (const int*)d_in[10];
    const int* pair_idx       = (const int*)d_in[11];

    int n = in_sizes[7];   // N rows

    int sm_count = 148;
    cudaDeviceGetAttribute(&sm_count, cudaDevAttrMultiProcessorCount, 0);

    // 6 blocks/SM x 256 threads: ALL blocks resident -> grid barrier is safe.
    fused_all_kernel<<<6 * sm_count, 256>>>(
        level_tab, type_tab, feature_tab, exchange_tab, pair_tab, W, b,
        level_idx, type_idx, feature_idx, exchange_idx, pair_idx,
        (float4*)d_out, n);
}